// round 1
// baseline (speedup 1.0000x reference)
#include <cuda_runtime.h>
#include <cuda_bf16.h>
#include <cstdint>

// Problem constants
#define T_ 15
#define CIN 6
#define HH 160
#define WW 160
#define F1 30
#define K1 5
#define THR1 15.0f
#define F2 250
#define K2 3
#define THR2 10.0f
#define KWTA 8
#define RADIUS 1
#define PH 80           // pooled H/W
#define IP 82           // padded pooled dim
#define FPAD 256        // padded channel count for layer-2 scratch
#define NHW (PH*PH)     // 6400

// -------- scratch (static device memory; no allocation at runtime) --------
__device__ float g_inp2[T_ * F1 * IP * IP];            // 12.1 MB, padded pooled spikes
__device__ float g_pot2[(size_t)T_ * NHW * FPAD];      // 98.3 MB, layout (t, hw, f)
__device__ float g_val[NHW];
__device__ int   g_nsp[NHW];
__device__ int   g_wf[NHW];
__device__ unsigned int g_maxbits;

// ===================== conv1 (5x5, pad2) + fire + 2x2 maxpool =====================
// grid (25 tiles, 30 c1, 15 t), block 256. One thread -> one pooled output pixel.
__global__ __launch_bounds__(256) void conv1_pool_k(const float* __restrict__ data,
                                                    const float* __restrict__ W1)
{
    __shared__ float sIn[CIN][36][36];   // 36x36 input window per channel
    __shared__ float sW[CIN * K1 * K1];

    const int t  = blockIdx.z;
    const int c1 = blockIdx.y;
    const int tile = blockIdx.x;
    const int ty0 = (tile / 5) * 16;     // pooled-tile origin
    const int tx0 = (tile % 5) * 16;
    const int tid = threadIdx.x;

    for (int i = tid; i < CIN * K1 * K1; i += 256)
        sW[i] = W1[c1 * CIN * K1 * K1 + i];

    const float* dbase = data + (size_t)t * CIN * HH * WW;
    for (int i = tid; i < CIN * 36 * 36; i += 256) {
        int c = i / 1296;
        int r = i % 1296;
        int iy = r / 36, ix = r % 36;
        int gy = ty0 * 2 - 2 + iy;
        int gx = tx0 * 2 - 2 + ix;
        float v = 0.f;
        if (gy >= 0 && gy < HH && gx >= 0 && gx < WW)
            v = dbase[(c * HH + gy) * WW + gx];
        sIn[c][iy][ix] = v;
    }
    __syncthreads();

    const int ty = tid / 16, tx = tid % 16;
    const int by = 2 * ty, bx = 2 * tx;

    float a00 = 0.f, a01 = 0.f, a10 = 0.f, a11 = 0.f;
#pragma unroll
    for (int c = 0; c < CIN; c++) {
#pragma unroll
        for (int ky = 0; ky < K1; ky++) {
#pragma unroll
            for (int kx = 0; kx < K1; kx++) {
                float w  = sW[(c * K1 + ky) * K1 + kx];
                float i00 = sIn[c][by + ky][bx + kx];
                float i01 = sIn[c][by + ky][bx + 1 + kx];
                float i10 = sIn[c][by + 1 + ky][bx + kx];
                float i11 = sIn[c][by + 1 + ky][bx + 1 + kx];
                a00 += i00 * w; a01 += i01 * w; a10 += i10 * w; a11 += i11 * w;
            }
        }
    }
    float sp = (a00 > THR1 || a01 > THR1 || a10 > THR1 || a11 > THR1) ? 1.f : 0.f;
    int py = ty0 + ty, px = tx0 + tx;
    g_inp2[((t * F1 + c1) * IP + (py + 1)) * IP + (px + 1)] = sp;
}

// ===================== conv2 (3x3 over padded pooled spikes) + fire =====================
// grid (25 tiles, 32 f-chunks, 15 t), block 128. Thread -> 2 pixels x 8 channels.
__global__ __launch_bounds__(128) void conv2_k(const float* __restrict__ W2)
{
    __shared__ float sIn[F1][18][18];    // 38880 B
    __shared__ float sW[8 * F1 * 9];     //  8640 B

    const int t = blockIdx.z;
    const int f0 = blockIdx.y * 8;
    const int tile = blockIdx.x;
    const int y0 = (tile / 5) * 16;
    const int x0 = (tile % 5) * 16;
    const int tid = threadIdx.x;

    const float* ibase = g_inp2 + (size_t)t * F1 * IP * IP;
    for (int i = tid; i < F1 * 324; i += 128) {
        int c = i / 324, r = i % 324;
        int iy = r / 18, ix = r % 18;
        sIn[c][iy][ix] = ibase[(c * IP + y0 + iy) * IP + (x0 + ix)];
    }
    for (int i = tid; i < 8 * F1 * 9; i += 128) {
        int f = f0 + i / (F1 * 9);
        sW[i] = (f < F2) ? W2[(size_t)f0 * F1 * 9 + i] : 0.f;
    }
    __syncthreads();

    const int ty = tid / 8;          // 0..15
    const int tx = tid % 8;          // 0..7 -> x = 2tx, 2tx+1

    float acc0[8], acc1[8];
#pragma unroll
    for (int j = 0; j < 8; j++) { acc0[j] = 0.f; acc1[j] = 0.f; }

    for (int c = 0; c < F1; c++) {
#pragma unroll
        for (int ky = 0; ky < 3; ky++) {
#pragma unroll
            for (int kx = 0; kx < 3; kx++) {
                float i0 = sIn[c][ty + ky][2 * tx + kx];
                float i1 = sIn[c][ty + ky][2 * tx + 1 + kx];
                int wb = (c * 9 + ky * 3 + kx);
#pragma unroll
                for (int j = 0; j < 8; j++) {
                    float w = sW[j * (F1 * 9) + wb];
                    acc0[j] += i0 * w;
                    acc1[j] += i1 * w;
                }
            }
        }
    }

    const int y = y0 + ty;
    {
        int x = x0 + 2 * tx;
        float* o = g_pot2 + ((size_t)t * NHW + (y * PH + x)) * FPAD + f0;
#pragma unroll
        for (int j = 0; j < 8; j++) { float v = acc0[j]; o[j] = (v > THR2) ? v : 0.f; }
    }
    {
        int x = x0 + 2 * tx + 1;
        float* o = g_pot2 + ((size_t)t * NHW + (y * PH + x)) * FPAD + f0;
#pragma unroll
        for (int j = 0; j < 8; j++) { float v = acc1[j]; o[j] = (v > THR2) ? v : 0.f; }
    }
}

// ===================== pointwise inhibition + sparse output scatter =====================
// grid 6400 blocks (one per (h,w)), block 256 threads (one per channel, f<250).
__global__ __launch_bounds__(256) void inhib_k(float* __restrict__ out)
{
    const int hw = blockIdx.x;
    const int tid = threadIdx.x;
    __shared__ unsigned long long sred[8];

    // load pot[t][hw][tid] for all t into registers
    float v[T_];
#pragma unroll
    for (int t = 0; t < T_; t++) {
        v[t] = (tid < F2) ? g_pot2[((size_t)t * NHW + hw) * FPAD + tid] : 0.f;
    }

    int S = 0, clamp14 = 0;
#pragma unroll
    for (int t = 0; t < T_; t++) {
        int any = __syncthreads_or(v[t] > 0.f);
        if (any) S++;
        if (t == T_ - 1) clamp14 = any ? 1 : 0;
    }
    int first_t = T_ - S;
    if (first_t < 0) first_t = 0;
    if (first_t > T_ - 1) first_t = T_ - 1;

    // argmax over channels at first_t (first-occurrence tie break -> min index)
    float mv = (tid < F2) ? g_pot2[((size_t)first_t * NHW + hw) * FPAD + tid] : -1.f;
    unsigned long long pk =
        ((unsigned long long)__float_as_uint(mv < 0.f ? 0.f : mv) << 32) |
        (unsigned long long)(0xFFFFFFFFu - (unsigned)tid);
    if (mv < 0.f) pk = 0;  // exclude padded channels entirely

    unsigned long long p = pk;
#pragma unroll
    for (int o = 16; o > 0; o >>= 1) {
        unsigned long long q = __shfl_down_sync(0xffffffffu, p, o);
        if (q > p) p = q;
    }
    int warp = tid >> 5, lane = tid & 31;
    if (lane == 0) sred[warp] = p;
    __syncthreads();
    if (warp == 0) {
        p = (lane < 8) ? sred[lane] : 0ull;
#pragma unroll
        for (int o = 16; o > 0; o >>= 1) {
            unsigned long long q = __shfl_down_sync(0xffffffffu, p, o);
            if (q > p) p = q;
        }
        if (lane == 0) sred[0] = p;
    }
    __syncthreads();
    unsigned long long best = sred[0];
    int wf = (int)(0xFFFFFFFFu - (unsigned)(best & 0xFFFFFFFFull));

    if (tid == 0) {
        if (clamp14) {
            float pv[T_];
#pragma unroll
            for (int t = 0; t < T_; t++)
                pv[t] = g_pot2[((size_t)t * NHW + hw) * FPAD + wf];
            int nsp = 0;
#pragma unroll
            for (int t = 0; t < T_; t++) if (pv[t] > 0.f) nsp++;

            int ft = T_ - nsp;
            if (ft < 0) ft = 0;
            if (ft > T_ - 1) ft = T_ - 1;
            float fval = pv[ft];

            // sparse scatter: spike2 then pot2 (rest of d_out already zero)
#pragma unroll
            for (int t = 0; t < T_; t++) {
                if (pv[t] > 0.f) {
                    size_t o = ((size_t)t * F2 + wf) * NHW + hw;
                    out[o] = 1.f;
                    out[(size_t)T_ * F2 * NHW + o] = pv[t];
                }
            }
            g_val[hw] = fval;
            g_nsp[hw] = nsp;
            g_wf[hw]  = wf;
            if (nsp > 0) atomicMax(&g_maxbits, __float_as_uint(fval));
        } else {
            g_val[hw] = 0.f;
            g_nsp[hw] = 0;
            g_wf[hw]  = 0;
        }
    }
}

// ===================== k-WTA (8 sequential global argmax + suppression) =====================
__global__ __launch_bounds__(1024) void winners_k(float* __restrict__ out)
{
    const int tid = threadIdx.x;
    __shared__ unsigned long long sred[32];

    float maxval = __uint_as_float(g_maxbits);
    float v15 = 15.f * maxval;

    float tot[7];
    int key[7], fh[7], hh[7], ww[7];
#pragma unroll
    for (int k = 0; k < 7; k++) {
        int idx = tid + k * 1024;
        if (idx < NHW) {
            int nsp = g_nsp[idx];
            float val = g_val[idx];
            int f = g_wf[idx];
            tot[k] = (nsp > 0) ? (float)nsp * (val + v15) : 0.f;
            fh[k] = f;
            hh[k] = idx / PH;
            ww[k] = idx % PH;
            key[k] = f * NHW + idx;
        } else {
            tot[k] = 0.f; key[k] = 0; fh[k] = -2; hh[k] = -100; ww[k] = -100;
        }
    }

    float* wout = out + (size_t)2 * T_ * F2 * NHW;

    for (int it = 0; it < KWTA; it++) {
        unsigned long long p = 0ull;
#pragma unroll
        for (int k = 0; k < 7; k++) {
            if (tot[k] > 0.f) {
                unsigned long long pk =
                    ((unsigned long long)__float_as_uint(tot[k]) << 32) |
                    (unsigned long long)(0x7FFFFFFFu - (unsigned)key[k]);
                if (pk > p) p = pk;
            }
        }
#pragma unroll
        for (int o = 16; o > 0; o >>= 1) {
            unsigned long long q = __shfl_down_sync(0xffffffffu, p, o);
            if (q > p) p = q;
        }
        int warp = tid >> 5, lane = tid & 31;
        if (lane == 0) sred[warp] = p;
        __syncthreads();
        if (warp == 0) {
            p = (lane < 32) ? sred[lane] : 0ull;
#pragma unroll
            for (int o = 16; o > 0; o >>= 1) {
                unsigned long long q = __shfl_down_sync(0xffffffffu, p, o);
                if (q > p) p = q;
            }
            if (lane == 0) sred[0] = p;
        }
        __syncthreads();
        unsigned long long best = sred[0];
        __syncthreads();  // sred reused next iteration

        if ((best >> 32) == 0ull) {
            if (tid == 0) {
                wout[it * 3 + 0] = -1.f;
                wout[it * 3 + 1] = -1.f;
                wout[it * 3 + 2] = -1.f;
            }
            continue;  // state unchanged; remaining iterations also invalid
        }
        int bkey = (int)(0x7FFFFFFFu - (unsigned)(best & 0xFFFFFFFFull));
        int bf = bkey / NHW;
        int bhw = bkey % NHW;
        int bh = bhw / PH, bw = bhw % PH;

        if (tid == 0) {
            wout[it * 3 + 0] = (float)bf;
            wout[it * 3 + 1] = (float)bh;
            wout[it * 3 + 2] = (float)bw;
        }

        // suppression: zero whole channel bf; zero all channels within radius of (bh,bw)
#pragma unroll
        for (int k = 0; k < 7; k++) {
            int dh = hh[k] - bh; if (dh < 0) dh = -dh;
            int dw = ww[k] - bw; if (dw < 0) dw = -dw;
            if (fh[k] == bf || (dh <= RADIUS && dw <= RADIUS)) tot[k] = 0.f;
        }
    }
}

// ===================== launch =====================
extern "C" void kernel_launch(void* const* d_in, const int* in_sizes, int n_in,
                              void* d_out, int out_size)
{
    const float* data = (const float*)d_in[0];
    const float* W1   = (const float*)d_in[1];
    const float* W2   = (const float*)d_in[2];
    float* out = (float*)d_out;

    void* p_inp2 = nullptr; void* p_maxbits = nullptr;
    cudaGetSymbolAddress(&p_inp2, g_inp2);
    cudaGetSymbolAddress(&p_maxbits, g_maxbits);

    cudaMemsetAsync(d_out, 0, (size_t)out_size * sizeof(float));
    cudaMemsetAsync(p_inp2, 0, sizeof(float) * T_ * F1 * IP * IP);
    cudaMemsetAsync(p_maxbits, 0, sizeof(unsigned int));

    dim3 g1(25, F1, T_);
    conv1_pool_k<<<g1, 256>>>(data, W1);

    dim3 g2(25, 32, T_);
    conv2_k<<<g2, 128>>>(W2);

    inhib_k<<<NHW, 256>>>(out);

    winners_k<<<1, 1024>>>(out);
}

// round 3
// speedup vs baseline: 1.5052x; 1.5052x over previous
#include <cuda_runtime.h>
#include <cuda_bf16.h>
#include <cstdint>

// Problem constants
#define T_ 15
#define CIN 6
#define HH 160
#define WW 160
#define F1 30
#define K1 5
#define THR1 15.0f
#define F2 250
#define K2 3
#define THR2 10.0f
#define KWTA 8
#define RADIUS 1
#define PH 80           // pooled H/W
#define IP 82           // padded pooled dim
#define FPAD 256        // padded channel count for layer-2 scratch
#define NHW (PH*PH)     // 6400

#define KREAL 270       // 30*3*3
#define KPAD  272       // padded to 16
#define NKS   17        // K chunks of 16
#define AW    136       // packed uint32 (bf16x2) per A row

// Dynamic SMEM layout for conv2 (byte offsets; base 1024-aligned)
#define SM_SIN  0                        // 3000 floats = 12000 B
#define SM_A0   12032                    // 128 x 136 uint32 = 69632 B
#define SM_A1   (12032 + 69632)          // 81664
#define SM_B    (81664 + 69632)          // 151296 ; 136 x 72 uint32 = 39168 B
#define SM_TOTAL (151296 + 39168)        // 190464

// -------- scratch (static device memory; no allocation at runtime) --------
__device__ float g_inp2[T_ * F1 * IP * IP];            // padded pooled spikes
__device__ float g_pot2[(size_t)T_ * NHW * FPAD];      // layout (t, hw, f)
__device__ float g_val[NHW];
__device__ int   g_nsp[NHW];
__device__ int   g_wf[NHW];
__device__ unsigned int g_maxbits;
__device__ uint32_t g_W2img[3 * 2 * 128 * AW];         // [ver][half][m][j] bf16x2 (low=even k)

// ===================== prep: 3-way bf16 split of W2 into packed images =====================
__global__ __launch_bounds__(256) void prep_w2_k(const float* __restrict__ W2)
{
    int idx = blockIdx.x * 256 + threadIdx.x;           // over 2*128*136 = 34816
    if (idx >= 2 * 128 * AW) return;
    int j = idx % AW;
    int m = (idx / AW) % 128;
    int h = idx / (AW * 128);
    int f = h * 128 + m;
    int k0 = 2 * j, k1 = 2 * j + 1;
    float w0 = 0.f, w1 = 0.f;
    if (f < F2) {
        if (k0 < KREAL) w0 = W2[(size_t)f * KREAL + k0];
        if (k1 < KREAL) w1 = W2[(size_t)f * KREAL + k1];
    }
    float r0 = w0, r1 = w1;
#pragma unroll
    for (int v = 0; v < 3; v++) {
        __nv_bfloat16 b0 = __float2bfloat16(r0);
        __nv_bfloat16 b1 = __float2bfloat16(r1);
        r0 -= __bfloat162float(b0);
        r1 -= __bfloat162float(b1);
        unsigned short s0 = *reinterpret_cast<unsigned short*>(&b0);
        unsigned short s1 = *reinterpret_cast<unsigned short*>(&b1);
        g_W2img[(((size_t)v * 2 + h) * 128 + m) * AW + j] =
            ((uint32_t)s1 << 16) | (uint32_t)s0;
    }
}

// ===================== conv1 (5x5, pad2) + fire + 2x2 maxpool =====================
__global__ __launch_bounds__(256) void conv1_pool_k(const float* __restrict__ data,
                                                    const float* __restrict__ W1)
{
    __shared__ float sIn[CIN][36][36];
    __shared__ float sW[CIN * K1 * K1];

    const int t  = blockIdx.z;
    const int c1 = blockIdx.y;
    const int tile = blockIdx.x;
    const int ty0 = (tile / 5) * 16;
    const int tx0 = (tile % 5) * 16;
    const int tid = threadIdx.x;

    for (int i = tid; i < CIN * K1 * K1; i += 256)
        sW[i] = W1[c1 * CIN * K1 * K1 + i];

    const float* dbase = data + (size_t)t * CIN * HH * WW;
    for (int i = tid; i < CIN * 36 * 36; i += 256) {
        int c = i / 1296;
        int r = i % 1296;
        int iy = r / 36, ix = r % 36;
        int gy = ty0 * 2 - 2 + iy;
        int gx = tx0 * 2 - 2 + ix;
        float v = 0.f;
        if (gy >= 0 && gy < HH && gx >= 0 && gx < WW)
            v = dbase[(c * HH + gy) * WW + gx];
        sIn[c][iy][ix] = v;
    }
    __syncthreads();

    const int ty = tid / 16, tx = tid % 16;
    const int by = 2 * ty, bx = 2 * tx;

    float a00 = 0.f, a01 = 0.f, a10 = 0.f, a11 = 0.f;
#pragma unroll
    for (int c = 0; c < CIN; c++) {
#pragma unroll
        for (int ky = 0; ky < K1; ky++) {
#pragma unroll
            for (int kx = 0; kx < K1; kx++) {
                float w  = sW[(c * K1 + ky) * K1 + kx];
                float i00 = sIn[c][by + ky][bx + kx];
                float i01 = sIn[c][by + ky][bx + 1 + kx];
                float i10 = sIn[c][by + 1 + ky][bx + kx];
                float i11 = sIn[c][by + 1 + ky][bx + 1 + kx];
                a00 += i00 * w; a01 += i01 * w; a10 += i10 * w; a11 += i11 * w;
            }
        }
    }
    float sp = (a00 > THR1 || a01 > THR1 || a10 > THR1 || a11 > THR1) ? 1.f : 0.f;
    int py = ty0 + ty, px = tx0 + tx;
    g_inp2[((t * F1 + c1) * IP + (py + 1)) * IP + (px + 1)] = sp;
}

// ===================== conv2 via mma.sync (bf16 3-split, fp32 acc) =====================
// grid (100 tiles, 2 f-halves, 15 t), block 256 (8 warps).
// CTA tile: 128 f x 64 px. Warp tile: 32 f x 32 px (m16n8k16 frags: 2m x 4n).
__device__ __forceinline__ void mma16816(float c[4], uint32_t a0, uint32_t a1,
                                         uint32_t a2, uint32_t a3,
                                         uint32_t b0, uint32_t b1)
{
    asm volatile(
        "mma.sync.aligned.m16n8k16.row.col.f32.bf16.bf16.f32 "
        "{%0,%1,%2,%3}, {%4,%5,%6,%7}, {%8,%9}, {%0,%1,%2,%3};"
        : "+f"(c[0]), "+f"(c[1]), "+f"(c[2]), "+f"(c[3])
        : "r"(a0), "r"(a1), "r"(a2), "r"(a3), "r"(b0), "r"(b1));
}

__global__ __launch_bounds__(256) void conv2_mma_k()
{
    extern __shared__ char smem[];
    const int t = blockIdx.z;
    const int half = blockIdx.y;
    const int tile = blockIdx.x;
    const int ty0 = (tile / 10) * 8;
    const int tx0 = (tile % 10) * 8;
    const int tid = threadIdx.x;
    const int w = tid >> 5;
    const int lane = tid & 31;
    const int q = lane & 3, l4 = lane >> 2;

    float* sIn = (float*)(smem + SM_SIN);                 // [30][10][10]

    // ---- stage input window ----
    const float* ib = g_inp2 + (size_t)t * F1 * IP * IP;
    for (int i = tid; i < 3000; i += 256) {
        int c = i / 100, r = i % 100;
        sIn[i] = ib[((size_t)c * IP + (ty0 + r / 10)) * IP + (tx0 + r % 10)];
    }

    // ---- stage A version 0 into buf0 (swizzled) ----
    {
        const uint4* src = (const uint4*)(g_W2img + ((size_t)(0 * 2 + half) * 128) * AW);
        uint32_t* dst = (uint32_t*)(smem + SM_A0);
#pragma unroll
        for (int it = 0; it < 17; it++) {
            int widx4 = it * 256 + tid;            // uint4 index
            uint4 d = src[widx4];
            int wofs = widx4 * 4;
            int row = wofs / AW;
            int j0  = wofs % AW;                   // multiple of 4
            int swz = ((row >> 2) & 1) << 2;
            *(uint4*)(dst + row * AW + (j0 ^ swz)) = d;
        }
    }
    __syncthreads();

    // ---- build B: packed bf16x2 Bp[j=136][n=64] stride 72 words ----
    {
        int n = tid >> 2, qq = tid & 3;
        int py = n >> 3, px = n & 7;
        int c0 = (qq * 30) >> 2;                  // 0,7,15,22
        int c1 = ((qq + 1) * 30) >> 2;            // 7,15,22,30
        unsigned short* Bh = (unsigned short*)(smem + SM_B);
        for (int c = c0; c < c1; c++) {
#pragma unroll
            for (int ky = 0; ky < 3; ky++) {
#pragma unroll
                for (int kx = 0; kx < 3; kx++) {
                    int k = c * 9 + ky * 3 + kx;
                    __nv_bfloat16 b = __float2bfloat16(sIn[c * 100 + (py + ky) * 10 + px + kx]);
                    Bh[((k >> 1) * 72 + n) * 2 + (k & 1)] = *(unsigned short*)&b;
                }
            }
        }
        if (qq == 3) ((uint32_t*)(smem + SM_B))[135 * 72 + n] = 0u;  // k=270,271 pad
    }
    __syncthreads();

    // ---- fragment address setup ----
    const int m0 = (w >> 1) * 32, n0 = (w & 1) * 32;
    const uint32_t* Bp = (const uint32_t*)(smem + SM_B);
    int boff = q * 72 + n0 + l4;                   // word offset, + ks*8*72 + nf*8 + kreg*4*72

    int arow[2][2];   // word offsets (klow reg), [mf][hi]
    int aoff4[2][2];  // delta words to khigh reg
#pragma unroll
    for (int mf = 0; mf < 2; mf++)
#pragma unroll
        for (int hi = 0; hi < 2; hi++) {
            int row = m0 + 16 * mf + 8 * hi + l4;
            int swz = ((row >> 2) & 1) << 2;
            arow[mf][hi]  = row * AW + (q ^ swz);
            aoff4[mf][hi] = ((q + 4) ^ swz) - (q ^ swz);   // +4 or -4
        }

    float acc[2][4][4];
#pragma unroll
    for (int mf = 0; mf < 2; mf++)
#pragma unroll
        for (int nf = 0; nf < 4; nf++)
#pragma unroll
            for (int r = 0; r < 4; r++) acc[mf][nf][r] = 0.f;

    // ---- main loop: 3 versions x 17 k-steps ----
    for (int v = 0; v < 3; v++) {
        // prefetch next version into the other buffer
        if (v < 2) {
            const uint4* src = (const uint4*)(g_W2img + ((size_t)((v + 1) * 2 + half) * 128) * AW);
            uint32_t* dst = (uint32_t*)(smem + (((v + 1) & 1) ? SM_A1 : SM_A0));
#pragma unroll
            for (int it = 0; it < 17; it++) {
                int widx4 = it * 256 + tid;
                uint4 d = src[widx4];
                int wofs = widx4 * 4;
                int row = wofs / AW;
                int j0  = wofs % AW;
                int swz = ((row >> 2) & 1) << 2;
                *(uint4*)(dst + row * AW + (j0 ^ swz)) = d;
            }
        }

        const uint32_t* Ap = (const uint32_t*)(smem + ((v & 1) ? SM_A1 : SM_A0));
#pragma unroll
        for (int ks = 0; ks < NKS; ks++) {
            uint32_t a[2][4];
#pragma unroll
            for (int mf = 0; mf < 2; mf++) {
#pragma unroll
                for (int hi = 0; hi < 2; hi++) {
                    int base = arow[mf][hi] + ks * 8;
                    a[mf][hi]     = Ap[base];
                    a[mf][2 + hi] = Ap[base + aoff4[mf][hi]];
                }
            }
#pragma unroll
            for (int nf = 0; nf < 4; nf++) {
                uint32_t b0 = Bp[boff + ks * 8 * 72 + nf * 8];
                uint32_t b1 = Bp[boff + ks * 8 * 72 + nf * 8 + 4 * 72];
#pragma unroll
                for (int mf = 0; mf < 2; mf++)
                    mma16816(acc[mf][nf], a[mf][0], a[mf][1], a[mf][2], a[mf][3], b0, b1);
            }
        }
        __syncthreads();   // next buffer fully staged; A buf v now reusable
    }

    // ---- epilogue: threshold + transpose via smem + coalesced store ----
    float* sD = (float*)(smem + SM_B);             // [64 px][stride 132] floats (33.8KB)
    // (B no longer needed; all reads done before last __syncthreads)
#pragma unroll
    for (int mf = 0; mf < 2; mf++) {
#pragma unroll
        for (int nf = 0; nf < 4; nf++) {
#pragma unroll
            for (int r = 0; r < 4; r++) {
                int fl = m0 + 16 * mf + 8 * ((r >> 1) & 1) + l4;
                int px = n0 + 8 * nf + 2 * q + (r & 1);
                float vv = acc[mf][nf][r];
                sD[px * 132 + fl] = (vv > THR2) ? vv : 0.f;
            }
        }
    }
    __syncthreads();
    {
        int pxl = tid >> 2;
        int fo = (tid & 3) * 32;
        int y = ty0 + (pxl >> 3), x = tx0 + (pxl & 7);
        float* o = g_pot2 + ((size_t)t * NHW + (size_t)(y * PH + x)) * FPAD + half * 128 + fo;
        const float* s = sD + pxl * 132 + fo;
#pragma unroll
        for (int j = 0; j < 8; j++)
            *(float4*)(o + j * 4) = *(const float4*)(s + j * 4);
    }
}

// ===================== pointwise inhibition + sparse output scatter =====================
__global__ __launch_bounds__(256) void inhib_k(float* __restrict__ out)
{
    const int hw = blockIdx.x;
    const int tid = threadIdx.x;
    __shared__ unsigned long long sred[8];

    float v[T_];
#pragma unroll
    for (int t = 0; t < T_; t++) {
        v[t] = (tid < F2) ? g_pot2[((size_t)t * NHW + hw) * FPAD + tid] : 0.f;
    }

    int S = 0, clamp14 = 0;
#pragma unroll
    for (int t = 0; t < T_; t++) {
        int any = __syncthreads_or(v[t] > 0.f);
        if (any) S++;
        if (t == T_ - 1) clamp14 = any ? 1 : 0;
    }
    int first_t = T_ - S;
    if (first_t < 0) first_t = 0;
    if (first_t > T_ - 1) first_t = T_ - 1;

    float mv = (tid < F2) ? g_pot2[((size_t)first_t * NHW + hw) * FPAD + tid] : -1.f;
    unsigned long long pk =
        ((unsigned long long)__float_as_uint(mv < 0.f ? 0.f : mv) << 32) |
        (unsigned long long)(0xFFFFFFFFu - (unsigned)tid);
    if (mv < 0.f) pk = 0;

    unsigned long long p = pk;
#pragma unroll
    for (int o = 16; o > 0; o >>= 1) {
        unsigned long long qq = __shfl_down_sync(0xffffffffu, p, o);
        if (qq > p) p = qq;
    }
    int warp = tid >> 5, lane = tid & 31;
    if (lane == 0) sred[warp] = p;
    __syncthreads();
    if (warp == 0) {
        p = (lane < 8) ? sred[lane] : 0ull;
#pragma unroll
        for (int o = 16; o > 0; o >>= 1) {
            unsigned long long qq = __shfl_down_sync(0xffffffffu, p, o);
            if (qq > p) p = qq;
        }
        if (lane == 0) sred[0] = p;
    }
    __syncthreads();
    unsigned long long best = sred[0];
    int wf = (int)(0xFFFFFFFFu - (unsigned)(best & 0xFFFFFFFFull));

    if (tid == 0) {
        if (clamp14) {
            float pv[T_];
#pragma unroll
            for (int t = 0; t < T_; t++)
                pv[t] = g_pot2[((size_t)t * NHW + hw) * FPAD + wf];
            int nsp = 0;
#pragma unroll
            for (int t = 0; t < T_; t++) if (pv[t] > 0.f) nsp++;

            int ft = T_ - nsp;
            if (ft < 0) ft = 0;
            if (ft > T_ - 1) ft = T_ - 1;
            float fval = pv[ft];

#pragma unroll
            for (int t = 0; t < T_; t++) {
                if (pv[t] > 0.f) {
                    size_t o = ((size_t)t * F2 + wf) * NHW + hw;
                    out[o] = 1.f;
                    out[(size_t)T_ * F2 * NHW + o] = pv[t];
                }
            }
            g_val[hw] = fval;
            g_nsp[hw] = nsp;
            g_wf[hw]  = wf;
            if (nsp > 0) atomicMax(&g_maxbits, __float_as_uint(fval));
        } else {
            g_val[hw] = 0.f;
            g_nsp[hw] = 0;
            g_wf[hw]  = 0;
        }
    }
}

// ===================== k-WTA =====================
__global__ __launch_bounds__(1024) void winners_k(float* __restrict__ out)
{
    const int tid = threadIdx.x;
    __shared__ unsigned long long sred[32];

    float maxval = __uint_as_float(g_maxbits);
    float v15 = 15.f * maxval;

    float tot[7];
    int key[7], fh[7], hh[7], ww[7];
#pragma unroll
    for (int k = 0; k < 7; k++) {
        int idx = tid + k * 1024;
        if (idx < NHW) {
            int nsp = g_nsp[idx];
            float val = g_val[idx];
            int f = g_wf[idx];
            tot[k] = (nsp > 0) ? (float)nsp * (val + v15) : 0.f;
            fh[k] = f;
            hh[k] = idx / PH;
            ww[k] = idx % PH;
            key[k] = f * NHW + idx;
        } else {
            tot[k] = 0.f; key[k] = 0; fh[k] = -2; hh[k] = -100; ww[k] = -100;
        }
    }

    float* wout = out + (size_t)2 * T_ * F2 * NHW;

    for (int it = 0; it < KWTA; it++) {
        unsigned long long p = 0ull;
#pragma unroll
        for (int k = 0; k < 7; k++) {
            if (tot[k] > 0.f) {
                unsigned long long pk =
                    ((unsigned long long)__float_as_uint(tot[k]) << 32) |
                    (unsigned long long)(0x7FFFFFFFu - (unsigned)key[k]);
                if (pk > p) p = pk;
            }
        }
#pragma unroll
        for (int o = 16; o > 0; o >>= 1) {
            unsigned long long qq = __shfl_down_sync(0xffffffffu, p, o);
            if (qq > p) p = qq;
        }
        int warp = tid >> 5, lane = tid & 31;
        if (lane == 0) sred[warp] = p;
        __syncthreads();
        if (warp == 0) {
            p = (lane < 32) ? sred[lane] : 0ull;
#pragma unroll
            for (int o = 16; o > 0; o >>= 1) {
                unsigned long long qq = __shfl_down_sync(0xffffffffu, p, o);
                if (qq > p) p = qq;
            }
            if (lane == 0) sred[0] = p;
        }
        __syncthreads();
        unsigned long long best = sred[0];
        __syncthreads();

        if ((best >> 32) == 0ull) {
            if (tid == 0) {
                wout[it * 3 + 0] = -1.f;
                wout[it * 3 + 1] = -1.f;
                wout[it * 3 + 2] = -1.f;
            }
            continue;
        }
        int bkey = (int)(0x7FFFFFFFu - (unsigned)(best & 0xFFFFFFFFull));
        int bf = bkey / NHW;
        int bhw = bkey % NHW;
        int bh = bhw / PH, bw = bhw % PH;

        if (tid == 0) {
            wout[it * 3 + 0] = (float)bf;
            wout[it * 3 + 1] = (float)bh;
            wout[it * 3 + 2] = (float)bw;
        }

#pragma unroll
        for (int k = 0; k < 7; k++) {
            int dh = hh[k] - bh; if (dh < 0) dh = -dh;
            int dw = ww[k] - bw; if (dw < 0) dw = -dw;
            if (fh[k] == bf || (dh <= RADIUS && dw <= RADIUS)) tot[k] = 0.f;
        }
    }
}

// ===================== launch =====================
extern "C" void kernel_launch(void* const* d_in, const int* in_sizes, int n_in,
                              void* d_out, int out_size)
{
    const float* data = (const float*)d_in[0];
    const float* W1   = (const float*)d_in[1];
    const float* W2   = (const float*)d_in[2];
    float* out = (float*)d_out;

    void* p_inp2 = nullptr; void* p_maxbits = nullptr;
    cudaGetSymbolAddress(&p_inp2, g_inp2);
    cudaGetSymbolAddress(&p_maxbits, g_maxbits);

    cudaFuncSetAttribute(conv2_mma_k, cudaFuncAttributeMaxDynamicSharedMemorySize, SM_TOTAL);

    cudaMemsetAsync(d_out, 0, (size_t)out_size * sizeof(float));
    cudaMemsetAsync(p_inp2, 0, sizeof(float) * T_ * F1 * IP * IP);
    cudaMemsetAsync(p_maxbits, 0, sizeof(unsigned int));

    prep_w2_k<<<(2 * 128 * AW + 255) / 256, 256>>>(W2);

    dim3 g1(25, F1, T_);
    conv1_pool_k<<<g1, 256>>>(data, W1);

    dim3 g2(100, 2, T_);
    conv2_mma_k<<<g2, 256, SM_TOTAL>>>();

    inhib_k<<<NHW, 256>>>(out);

    winners_k<<<1, 1024>>>(out);
}

// round 5
// speedup vs baseline: 2.4425x; 1.6226x over previous
#include <cuda_runtime.h>
#include <cuda_bf16.h>
#include <cstdint>

// Problem constants
#define T_ 15
#define CIN 6
#define HH 160
#define WW 160
#define F1 30
#define K1 5
#define THR1 15.0f
#define F2 250
#define K2 3
#define THR2 10.0f
#define KWTA 8
#define RADIUS 1
#define PH 80           // pooled H/W
#define IP 82           // padded pooled dim
#define FPAD 256        // padded channel count for layer-2 scratch
#define NHW (PH*PH)     // 6400

#define KREAL 270       // 30*3*3
#define NKS   17        // K chunks of 16

// conv2 dynamic smem layout (bytes)
#define SM2_SIN 0                 // 3000 floats = 12000 B
#define SM2_B   12032             // 136 x 72 words = 39168 B
#define SM2_A   51200             // 3 stages x 12288 B = 36864
#define SM2_TOTAL 88064

// -------- scratch (static device memory; no allocation at runtime) --------
__device__ float g_inp2[T_ * F1 * IP * IP];            // padded pooled spikes
__device__ float g_pot2[(size_t)T_ * NHW * FPAD];      // layout (t, hw, f)
__device__ float g_val[NHW];
__device__ int   g_nsp[NHW];
__device__ int   g_wf[NHW];
__device__ unsigned int g_maxbits;
__device__ unsigned long long g_am[T_ * NHW];          // per (t,hw) argmax keys
// blocked+swizzled weight image: [half][ks][v][row 128][8 words]
__device__ uint32_t g_W2A[2 * NKS * 3 * 1024];

__device__ __forceinline__ uint32_t smem_u32(const void* p) {
    uint32_t a;
    asm("{ .reg .u64 t; cvta.to.shared.u64 t, %1; cvt.u32.u64 %0, t; }" : "=r"(a) : "l"(p));
    return a;
}
__device__ __forceinline__ void mma16816(float c[4], uint32_t a0, uint32_t a1,
                                         uint32_t a2, uint32_t a3,
                                         uint32_t b0, uint32_t b1)
{
    asm volatile(
        "mma.sync.aligned.m16n8k16.row.col.f32.bf16.bf16.f32 "
        "{%0,%1,%2,%3}, {%4,%5,%6,%7}, {%8,%9}, {%0,%1,%2,%3};"
        : "+f"(c[0]), "+f"(c[1]), "+f"(c[2]), "+f"(c[3])
        : "r"(a0), "r"(a1), "r"(a2), "r"(a3), "r"(b0), "r"(b1));
}
__device__ __forceinline__ void ldmx4(uint32_t r[4], uint32_t addr) {
    asm volatile("ldmatrix.sync.aligned.m8n8.x4.shared.b16 {%0,%1,%2,%3}, [%4];"
        : "=r"(r[0]), "=r"(r[1]), "=r"(r[2]), "=r"(r[3]) : "r"(addr));
}

// ===================== prep: 3-way bf16 split into blocked+swizzled image =====================
__global__ __launch_bounds__(256) void prep_w2_k(const float* __restrict__ W2)
{
    int idx = blockIdx.x * 256 + threadIdx.x;      // over 2*17*128*8 = 34816
    if (idx >= 2 * NKS * 128 * 8) return;
    int j   = idx & 7;
    int row = (idx >> 3) & 127;
    int ks  = ((idx >> 3) >> 7) % NKS;
    int half = ((idx >> 3) >> 7) / NKS;
    int kp = ks * 8 + j;                           // packed-k index
    int k0 = 2 * kp, k1 = k0 + 1;
    int f = half * 128 + row;
    float w0 = 0.f, w1 = 0.f;
    if (f < F2) {
        if (k0 < KREAL) w0 = W2[(size_t)f * KREAL + k0];
        if (k1 < KREAL) w1 = W2[(size_t)f * KREAL + k1];
    }
    int swz = ((row >> 2) & 1) << 2;
    int jx = j ^ swz;
    float r0 = w0, r1 = w1;
#pragma unroll
    for (int v = 0; v < 3; v++) {
        __nv_bfloat16 b0 = __float2bfloat16(r0);
        __nv_bfloat16 b1 = __float2bfloat16(r1);
        r0 -= __bfloat162float(b0);
        r1 -= __bfloat162float(b1);
        unsigned short s0 = *reinterpret_cast<unsigned short*>(&b0);
        unsigned short s1 = *reinterpret_cast<unsigned short*>(&b1);
        g_W2A[(((size_t)(half * NKS + ks)) * 3 + v) * 1024 + row * 8 + jx] =
            ((uint32_t)s1 << 16) | (uint32_t)s0;
    }
}

// ===================== conv1: all 30 channels per CTA, 8f x 4px blocking =====================
// grid (50 tiles, 15 t), block 128 = 16x8 pooled px
__global__ __launch_bounds__(128) void conv1_pool_k(const float* __restrict__ data,
                                                    const float* __restrict__ W1)
{
    __shared__ float sIn[CIN * 20 * 36];   // window: 20 rows x 36 cols per channel
    __shared__ float sW[32 * 150];

    const int t = blockIdx.y;
    const int tile = blockIdx.x;
    const int ty0 = (tile / 5) * 8;        // pooled origin
    const int tx0 = (tile % 5) * 16;
    const int tid = threadIdx.x;

    for (int i = tid; i < 32 * 150; i += 128) {
        int f = i / 150;
        sW[i] = (f < F1) ? W1[i] : 0.f;
    }
    const float* dbase = data + (size_t)t * CIN * HH * WW;
    for (int i = tid; i < CIN * 720; i += 128) {
        int c = i / 720, rr = i % 720;
        int r = rr / 36, s = rr % 36;
        int gy = 2 * ty0 - 2 + r, gx = 2 * tx0 - 2 + s;
        float v = 0.f;
        if (gy >= 0 && gy < HH && gx >= 0 && gx < WW)
            v = dbase[(c * HH + gy) * WW + gx];
        sIn[i] = v;
    }
    __syncthreads();

    const int ty = tid >> 4, tx = tid & 15;
    const int py = ty0 + ty, px = tx0 + tx;

    for (int fg = 0; fg < 4; fg++) {
        float acc[4][8];
#pragma unroll
        for (int i = 0; i < 4; i++)
#pragma unroll
            for (int f = 0; f < 8; f++) acc[i][f] = 0.f;

        for (int c = 0; c < CIN; c++) {
#pragma unroll
            for (int ky = 0; ky < K1; ky++) {
#pragma unroll
                for (int kx = 0; kx < K1; kx++) {
                    const float* sp = &sIn[c * 720 + (2 * ty + ky) * 36 + 2 * tx + kx];
                    float i00 = sp[0], i01 = sp[1], i10 = sp[36], i11 = sp[37];
                    int wi = c * 25 + ky * 5 + kx;
#pragma unroll
                    for (int f = 0; f < 8; f++) {
                        float wv = sW[(fg * 8 + f) * 150 + wi];
                        acc[0][f] += i00 * wv; acc[1][f] += i01 * wv;
                        acc[2][f] += i10 * wv; acc[3][f] += i11 * wv;
                    }
                }
            }
        }
#pragma unroll
        for (int f = 0; f < 8; f++) {
            int fc = fg * 8 + f;
            if (fc < F1) {
                float sp = (acc[0][f] > THR1 || acc[1][f] > THR1 ||
                            acc[2][f] > THR1 || acc[3][f] > THR1) ? 1.f : 0.f;
                g_inp2[((t * F1 + fc) * IP + (py + 1)) * IP + (px + 1)] = sp;
            }
        }
    }
}

// ===================== conv2: mma.sync + cp.async pipeline + B reuse =====================
// grid (100 tiles, 2 f-halves, 15 t), block 256 (8 warps).
__global__ __launch_bounds__(256) void conv2_mma_k()
{
    extern __shared__ char smem[];
    const uint32_t sb = smem_u32(smem);
    const int t = blockIdx.z;
    const int half = blockIdx.y;
    const int tile = blockIdx.x;
    const int ty0 = (tile / 10) * 8;
    const int tx0 = (tile % 10) * 8;
    const int tid = threadIdx.x;
    const int w = tid >> 5;
    const int lane = tid & 31;
    const int q = lane & 3, l4 = lane >> 2;

    const char* gA = ((const char*)g_W2A) + (size_t)half * NKS * 3 * 4096;

    // prologue: prefetch stages 0,1
#pragma unroll
    for (int p = 0; p < 2; p++) {
        uint32_t dst = sb + SM2_A + p * 12288 + tid * 16;
        const char* src = gA + (size_t)p * 12288 + tid * 16;
#pragma unroll
        for (int i = 0; i < 3; i++)
            asm volatile("cp.async.cg.shared.global [%0], [%1], 16;"
                :: "r"(dst + i * 4096), "l"(src + (size_t)i * 4096));
        asm volatile("cp.async.commit_group;" ::: "memory");
    }

    // stage input window
    float* sIn = (float*)(smem + SM2_SIN);
    const float* ib = g_inp2 + (size_t)t * F1 * IP * IP;
    for (int i = tid; i < 3000; i += 256) {
        int c = i / 100, r = i % 100;
        sIn[i] = ib[((size_t)c * IP + (ty0 + r / 10)) * IP + (tx0 + r % 10)];
    }
    __syncthreads();

    // build B: packed bf16x2 [j=k/2 (136)][n=64] stride 72 words
    {
        int n = tid >> 2, qq = tid & 3;
        int py = n >> 3, px = n & 7;
        int c0 = (qq * 30) >> 2;
        int c1 = ((qq + 1) * 30) >> 2;
        unsigned short* Bh = (unsigned short*)(smem + SM2_B);
        for (int c = c0; c < c1; c++) {
#pragma unroll
            for (int ky = 0; ky < 3; ky++) {
#pragma unroll
                for (int kx = 0; kx < 3; kx++) {
                    int k = c * 9 + ky * 3 + kx;
                    __nv_bfloat16 b = __float2bfloat16(sIn[c * 100 + (py + ky) * 10 + px + kx]);
                    Bh[((k >> 1) * 72 + n) * 2 + (k & 1)] = *(unsigned short*)&b;
                }
            }
        }
        if (qq == 3) ((uint32_t*)(smem + SM2_B))[135 * 72 + n] = 0u;   // k=270,271 pad
    }

    // fragment addressing
    const int m0 = (w >> 1) * 32, n0 = (w & 1) * 32;
    const uint32_t* Bp = (const uint32_t*)(smem + SM2_B);
    const int boff = q * 72 + n0 + l4;
    const int row_l = m0 + (lane & 15);
    const uint32_t a_off = (uint32_t)(row_l * 8 +
                         ((((lane >> 4) << 2) ^ (((row_l >> 2) & 1) << 2)))) * 4;
    const uint32_t aBase = sb + SM2_A + a_off;

    float acc[2][4][4];
#pragma unroll
    for (int mf = 0; mf < 2; mf++)
#pragma unroll
        for (int nf = 0; nf < 4; nf++)
#pragma unroll
            for (int r = 0; r < 4; r++) acc[mf][nf][r] = 0.f;

    // main loop: ks outer (B reused), v inner
    for (int ks = 0; ks < NKS; ks++) {
        asm volatile("cp.async.wait_group 1;" ::: "memory");
        __syncthreads();

        uint32_t b0[4], b1[4];
#pragma unroll
        for (int nf = 0; nf < 4; nf++) {
            int o = boff + ks * 576 + nf * 8;
            b0[nf] = Bp[o];
            b1[nf] = Bp[o + 288];
        }
        uint32_t abase = aBase + (uint32_t)(ks % 3) * 12288;
#pragma unroll
        for (int v = 0; v < 3; v++) {
            uint32_t a0[4], a1[4];
            ldmx4(a0, abase + v * 4096);
            ldmx4(a1, abase + v * 4096 + 512);
#pragma unroll
            for (int nf = 0; nf < 4; nf++) {
                mma16816(acc[0][nf], a0[0], a0[1], a0[2], a0[3], b0[nf], b1[nf]);
                mma16816(acc[1][nf], a1[0], a1[1], a1[2], a1[3], b0[nf], b1[nf]);
            }
        }
        if (ks + 2 < NKS) {
            int nk = ks + 2;
            uint32_t dst = sb + SM2_A + (uint32_t)(nk % 3) * 12288 + tid * 16;
            const char* src = gA + (size_t)nk * 12288 + tid * 16;
#pragma unroll
            for (int i = 0; i < 3; i++)
                asm volatile("cp.async.cg.shared.global [%0], [%1], 16;"
                    :: "r"(dst + i * 4096), "l"(src + (size_t)i * 4096));
        }
        asm volatile("cp.async.commit_group;" ::: "memory");
    }

    // threshold in place
#pragma unroll
    for (int mf = 0; mf < 2; mf++)
#pragma unroll
        for (int nf = 0; nf < 4; nf++)
#pragma unroll
            for (int r = 0; r < 4; r++) {
                float v = acc[mf][nf][r];
                acc[mf][nf][r] = (v > THR2) ? v : 0.f;
            }

    // per-(t,hw) argmax keys: shfl pre-reduce over l4, atomicMax to global
#pragma unroll
    for (int nf = 0; nf < 4; nf++) {
#pragma unroll
        for (int lh = 0; lh < 2; lh++) {
            unsigned long long key = 0ull;
#pragma unroll
            for (int mf = 0; mf < 2; mf++)
#pragma unroll
                for (int hi = 0; hi < 2; hi++) {
                    float tv = acc[mf][nf][(hi << 1) | lh];
                    unsigned fg = (unsigned)(half * 128 + m0 + 16 * mf + 8 * hi + l4);
                    unsigned long long k =
                        ((unsigned long long)__float_as_uint(tv) << 32) | (255u - fg);
                    if (k > key) key = k;
                }
#pragma unroll
            for (int msk = 4; msk <= 16; msk <<= 1) {
                unsigned long long o = __shfl_xor_sync(0xffffffffu, key, msk);
                if (o > key) key = o;
            }
            if (l4 == 0) {
                int px = n0 + 8 * nf + 2 * q + lh;
                int hw = (ty0 + (px >> 3)) * PH + tx0 + (px & 7);
                atomicMax(&g_am[t * NHW + hw], key);
            }
        }
    }

    __syncthreads();   // all B reads done; reuse SM2_B as transpose buffer

    float* sD = (float*)(smem + SM2_B);           // [64 px][stride 132]
#pragma unroll
    for (int mf = 0; mf < 2; mf++)
#pragma unroll
        for (int nf = 0; nf < 4; nf++)
#pragma unroll
            for (int r = 0; r < 4; r++) {
                int fl = m0 + 16 * mf + 8 * ((r >> 1) & 1) + l4;
                int px = n0 + 8 * nf + 2 * q + (r & 1);
                sD[px * 132 + fl] = acc[mf][nf][r];
            }
    __syncthreads();
    {
        int pxl = tid >> 2;
        int fo = (tid & 3) * 32;
        int y = ty0 + (pxl >> 3), x = tx0 + (pxl & 7);
        float* o = g_pot2 + ((size_t)t * NHW + (size_t)(y * PH + x)) * FPAD + half * 128 + fo;
        const float* s = sD + pxl * 132 + fo;
#pragma unroll
        for (int j = 0; j < 8; j++)
            *(float4*)(o + j * 4) = *(const float4*)(s + j * 4);
    }
}

// ===================== pointwise inhibition (key-based) + sparse scatter =====================
__global__ __launch_bounds__(256) void inhib_k(float* __restrict__ out)
{
    int hw = blockIdx.x * 256 + threadIdx.x;
    if (hw >= NHW) return;

    int S = 0;
    unsigned long long klast = 0ull;
#pragma unroll
    for (int t = 0; t < T_; t++) {
        unsigned long long k = g_am[t * NHW + hw];
        if ((k >> 32) != 0ull) S++;
        if (t == T_ - 1) klast = k;
    }
    int clamp14 = ((klast >> 32) != 0ull) ? 1 : 0;
    int ft0 = T_ - S;
    if (ft0 < 0) ft0 = 0;
    if (ft0 > T_ - 1) ft0 = T_ - 1;
    unsigned long long kf = g_am[ft0 * NHW + hw];
    int wf = 255 - (int)(kf & 0xFFFFFFFFull);

    if (clamp14) {
        float pv[T_];
        int nsp = 0;
#pragma unroll
        for (int t = 0; t < T_; t++) {
            pv[t] = g_pot2[((size_t)t * NHW + hw) * FPAD + wf];
            if (pv[t] > 0.f) nsp++;
        }
        int ft = T_ - nsp;
        if (ft < 0) ft = 0;
        if (ft > T_ - 1) ft = T_ - 1;
        float fval = pv[ft];
#pragma unroll
        for (int t = 0; t < T_; t++) {
            if (pv[t] > 0.f) {
                size_t o = ((size_t)t * F2 + wf) * NHW + hw;
                out[o] = 1.f;
                out[(size_t)T_ * F2 * NHW + o] = pv[t];
            }
        }
        g_val[hw] = fval;
        g_nsp[hw] = nsp;
        g_wf[hw]  = wf;
        if (nsp > 0) atomicMax(&g_maxbits, __float_as_uint(fval));
    } else {
        g_val[hw] = 0.f;
        g_nsp[hw] = 0;
        g_wf[hw]  = 0;
    }
}

// ===================== k-WTA =====================
__global__ __launch_bounds__(1024) void winners_k(float* __restrict__ out)
{
    const int tid = threadIdx.x;
    __shared__ unsigned long long sred[32];

    float maxval = __uint_as_float(g_maxbits);
    float v15 = 15.f * maxval;

    float tot[7];
    int key[7], fh[7], hh[7], ww[7];
#pragma unroll
    for (int k = 0; k < 7; k++) {
        int idx = tid + k * 1024;
        if (idx < NHW) {
            int nsp = g_nsp[idx];
            float val = g_val[idx];
            int f = g_wf[idx];
            tot[k] = (nsp > 0) ? (float)nsp * (val + v15) : 0.f;
            fh[k] = f;
            hh[k] = idx / PH;
            ww[k] = idx % PH;
            key[k] = f * NHW + idx;
        } else {
            tot[k] = 0.f; key[k] = 0; fh[k] = -2; hh[k] = -100; ww[k] = -100;
        }
    }

    float* wout = out + (size_t)2 * T_ * F2 * NHW;

    for (int it = 0; it < KWTA; it++) {
        unsigned long long p = 0ull;
#pragma unroll
        for (int k = 0; k < 7; k++) {
            if (tot[k] > 0.f) {
                unsigned long long pk =
                    ((unsigned long long)__float_as_uint(tot[k]) << 32) |
                    (unsigned long long)(0x7FFFFFFFu - (unsigned)key[k]);
                if (pk > p) p = pk;
            }
        }
#pragma unroll
        for (int o = 16; o > 0; o >>= 1) {
            unsigned long long qq = __shfl_down_sync(0xffffffffu, p, o);
            if (qq > p) p = qq;
        }
        int warp = tid >> 5, lane = tid & 31;
        if (lane == 0) sred[warp] = p;
        __syncthreads();
        if (warp == 0) {
            p = (lane < 32) ? sred[lane] : 0ull;
#pragma unroll
            for (int o = 16; o > 0; o >>= 1) {
                unsigned long long qq = __shfl_down_sync(0xffffffffu, p, o);
                if (qq > p) p = qq;
            }
            if (lane == 0) sred[0] = p;
        }
        __syncthreads();
        unsigned long long best = sred[0];
        __syncthreads();

        if ((best >> 32) == 0ull) {
            if (tid == 0) {
                wout[it * 3 + 0] = -1.f;
                wout[it * 3 + 1] = -1.f;
                wout[it * 3 + 2] = -1.f;
            }
            continue;
        }
        int bkey = (int)(0x7FFFFFFFu - (unsigned)(best & 0xFFFFFFFFull));
        int bf = bkey / NHW;
        int bhw = bkey % NHW;
        int bh = bhw / PH, bw = bhw % PH;

        if (tid == 0) {
            wout[it * 3 + 0] = (float)bf;
            wout[it * 3 + 1] = (float)bh;
            wout[it * 3 + 2] = (float)bw;
        }

#pragma unroll
        for (int k = 0; k < 7; k++) {
            int dh = hh[k] - bh; if (dh < 0) dh = -dh;
            int dw = ww[k] - bw; if (dw < 0) dw = -dw;
            if (fh[k] == bf || (dh <= RADIUS && dw <= RADIUS)) tot[k] = 0.f;
        }
    }
}

// ===================== launch =====================
extern "C" void kernel_launch(void* const* d_in, const int* in_sizes, int n_in,
                              void* d_out, int out_size)
{
    const float* data = (const float*)d_in[0];
    const float* W1   = (const float*)d_in[1];
    const float* W2   = (const float*)d_in[2];
    float* out = (float*)d_out;

    void* p_inp2 = nullptr; void* p_maxbits = nullptr; void* p_am = nullptr;
    cudaGetSymbolAddress(&p_inp2, g_inp2);
    cudaGetSymbolAddress(&p_maxbits, g_maxbits);
    cudaGetSymbolAddress(&p_am, g_am);

    cudaFuncSetAttribute(conv2_mma_k, cudaFuncAttributeMaxDynamicSharedMemorySize, SM2_TOTAL);

    cudaMemsetAsync(d_out, 0, (size_t)out_size * sizeof(float));
    cudaMemsetAsync(p_inp2, 0, sizeof(float) * T_ * F1 * IP * IP);
    cudaMemsetAsync(p_am, 0, sizeof(unsigned long long) * T_ * NHW);
    cudaMemsetAsync(p_maxbits, 0, sizeof(unsigned int));

    prep_w2_k<<<(2 * NKS * 128 * 8 + 255) / 256, 256>>>(W2);

    dim3 g1(50, T_);
    conv1_pool_k<<<g1, 128>>>(data, W1);

    dim3 g2(100, 2, T_);
    conv2_mma_k<<<g2, 256, SM2_TOTAL>>>();

    inhib_k<<<(NHW + 255) / 256, 256>>>(out);

    winners_k<<<1, 1024>>>(out);
}

// round 6
// speedup vs baseline: 2.5429x; 1.0411x over previous
#include <cuda_runtime.h>
#include <cuda_bf16.h>
#include <cstdint>

// Problem constants
#define T_ 15
#define CIN 6
#define HH 160
#define WW 160
#define F1 30
#define K1 5
#define THR1 15.0f
#define F2 250
#define K2 3
#define THR2 10.0f
#define KWTA 8
#define RADIUS 1
#define PH 80           // pooled H/W
#define IP 82           // padded pooled dim
#define FPAD 256        // padded channel count for layer-2 scratch
#define NHW (PH*PH)     // 6400

#define KREAL 270       // 30*3*3
#define NKS   17        // conv2 K chunks of 16

// conv2 dynamic smem layout (bytes)
#define SM2_SIN 0                 // 3000 floats = 12000 B
#define SM2_B   12032             // 136 x 72 words = 39168 B
#define SM2_A   51200             // 3 stages x 12288 B = 36864
#define SM2_TOTAL 88064

// conv1 dynamic smem layout (bytes)
#define SM1_A   0                 // 10*3*32*8 words = 30720 B
#define SM1_IN  30720             // 1440 floats = 5760 B
#define SM1_B   36480             // 80*136 words = 43520 B
#define SM1_SP  80000             // 128*32 bytes = 4096 B
#define SM1_TOTAL 84096

// -------- scratch (static device memory; no allocation at runtime) --------
__device__ float g_inp2[T_ * F1 * IP * IP];            // padded pooled spikes
__device__ float g_pot2[(size_t)T_ * NHW * FPAD];      // layout (t, hw, f)
__device__ float g_val[NHW];
__device__ int   g_nsp[NHW];
__device__ int   g_wf[NHW];
__device__ unsigned int g_maxbits;
__device__ unsigned long long g_am[T_ * NHW];          // per (t,hw) argmax keys
// conv2 weight image: [half][ks][v][row 128][8 words], swizzled
__device__ uint32_t g_W2A[2 * NKS * 3 * 1024];
// conv1 weight image: [ks 10][v 3][row 32][8 words], swizzled
__device__ uint32_t g_W1A[10 * 3 * 32 * 8];

__device__ __forceinline__ uint32_t smem_u32(const void* p) {
    uint32_t a;
    asm("{ .reg .u64 t; cvta.to.shared.u64 t, %1; cvt.u32.u64 %0, t; }" : "=r"(a) : "l"(p));
    return a;
}
__device__ __forceinline__ void mma16816(float c[4], uint32_t a0, uint32_t a1,
                                         uint32_t a2, uint32_t a3,
                                         uint32_t b0, uint32_t b1)
{
    asm volatile(
        "mma.sync.aligned.m16n8k16.row.col.f32.bf16.bf16.f32 "
        "{%0,%1,%2,%3}, {%4,%5,%6,%7}, {%8,%9}, {%0,%1,%2,%3};"
        : "+f"(c[0]), "+f"(c[1]), "+f"(c[2]), "+f"(c[3])
        : "r"(a0), "r"(a1), "r"(a2), "r"(a3), "r"(b0), "r"(b1));
}
__device__ __forceinline__ void ldmx4(uint32_t r[4], uint32_t addr) {
    asm volatile("ldmatrix.sync.aligned.m8n8.x4.shared.b16 {%0,%1,%2,%3}, [%4];"
        : "=r"(r[0]), "=r"(r[1]), "=r"(r[2]), "=r"(r[3]) : "r"(addr));
}
__device__ __forceinline__ uint32_t bf16pack(float a, float b) {
    __nv_bfloat16 b0 = __float2bfloat16(a);
    __nv_bfloat16 b1 = __float2bfloat16(b);
    unsigned short s0 = *reinterpret_cast<unsigned short*>(&b0);
    unsigned short s1 = *reinterpret_cast<unsigned short*>(&b1);
    return ((uint32_t)s1 << 16) | (uint32_t)s0;
}

// ===================== prep: weight images + scratch zeroing (one kernel) =====================
// grid 136 x 256 = 34816 threads
__global__ __launch_bounds__(256) void prep_k(const float* __restrict__ W1,
                                              const float* __restrict__ W2)
{
    const int gid = blockIdx.x * 256 + threadIdx.x;
    const int NT = 136 * 256;

    // conv2 weight image (3-way bf16 split)
    if (gid < 2 * NKS * 128 * 8) {
        int j   = gid & 7;
        int row = (gid >> 3) & 127;
        int ks  = ((gid >> 3) >> 7) % NKS;
        int half = ((gid >> 3) >> 7) / NKS;
        int kp = ks * 8 + j;
        int k0 = 2 * kp, k1 = k0 + 1;
        int f = half * 128 + row;
        float w0 = 0.f, w1 = 0.f;
        if (f < F2) {
            if (k0 < KREAL) w0 = W2[(size_t)f * KREAL + k0];
            if (k1 < KREAL) w1 = W2[(size_t)f * KREAL + k1];
        }
        int jx = j ^ (((row >> 2) & 1) << 2);
        float r0 = w0, r1 = w1;
#pragma unroll
        for (int v = 0; v < 3; v++) {
            uint32_t p = bf16pack(r0, r1);
            r0 -= __bfloat162float(__float2bfloat16(r0));
            r1 -= __bfloat162float(__float2bfloat16(r1));
            g_W2A[(((size_t)(half * NKS + ks)) * 3 + v) * 1024 + row * 8 + jx] = p;
        }
    }

    // conv1 weight image (3-way bf16 split), 2560 entries
    if (gid < 10 * 32 * 8) {
        int jw = gid & 7;
        int row = (gid >> 3) & 31;
        int ks = gid >> 8;
        int kp = ks * 8 + jw;
        int k0 = 2 * kp, k1 = k0 + 1;
        float w0 = 0.f, w1 = 0.f;
        if (row < F1) {
            if (k0 < 150) w0 = W1[row * 150 + k0];
            if (k1 < 150) w1 = W1[row * 150 + k1];
        }
        int jx = jw ^ (((row >> 2) & 1) << 2);
        float r0 = w0, r1 = w1;
#pragma unroll
        for (int v = 0; v < 3; v++) {
            uint32_t p = bf16pack(r0, r1);
            r0 -= __bfloat162float(__float2bfloat16(r0));
            r1 -= __bfloat162float(__float2bfloat16(r1));
            g_W1A[((ks * 3 + v) * 32 + row) * 8 + jx] = p;
        }
    }

    // zero g_inp2 (3,025,800 floats = 756,450 float4)
    float4 z = make_float4(0.f, 0.f, 0.f, 0.f);
    for (int i = gid; i < 756450; i += NT)
        ((float4*)g_inp2)[i] = z;
    // zero g_am
    for (int i = gid; i < T_ * NHW; i += NT)
        g_am[i] = 0ull;
    if (gid == 0) g_maxbits = 0u;
}

// ===================== conv1 via mma.sync + fused d_out zeroing =====================
// grid (200 tiles, 15 t), block 256 (8 warps). Tile = 16x8 conv px (8x4 pooled).
// GEMM: M=32 filters, K=160 (150 padded), N=128 px, 3 weight versions.
__global__ __launch_bounds__(256) void conv1_mma_k(const float* __restrict__ data,
                                                   float* __restrict__ outz, int nf4)
{
    extern __shared__ char smem[];
    const uint32_t sb = smem_u32(smem);
    const int t = blockIdx.y;
    const int tile = blockIdx.x;
    const int ty0 = (tile / 20) * 16;    // conv-space origin
    const int tx0 = (tile % 20) * 8;
    const int tid = threadIdx.x;
    const int w = tid >> 5, lane = tid & 31;
    const int q = lane & 3, l4 = lane >> 2;

    // async-load conv1 weight image (30720 B)
    for (int i = tid; i < 1920; i += 256)
        asm volatile("cp.async.cg.shared.global [%0], [%1], 16;"
            :: "r"(sb + SM1_A + i * 16), "l"((const char*)g_W1A + (size_t)i * 16));
    asm volatile("cp.async.commit_group;" ::: "memory");

    // zero a slice of d_out (spread across the whole grid; conv1 has spare DRAM BW)
    {
        const float4 z = make_float4(0.f, 0.f, 0.f, 0.f);
        float4* o4 = (float4*)outz;
        for (int i = (t * 200 + tile) * 256 + tid; i < nf4; i += 200 * T_ * 256)
            o4[i] = z;
    }

    // stage input window: 6 ch x 20 rows x 12 cols
    float* sIn = (float*)(smem + SM1_IN);
    const float* dbase = data + (size_t)t * CIN * HH * WW;
    for (int i = tid; i < 1440; i += 256) {
        int c = i / 240, rr = i % 240;
        int iy = rr / 12, ix = rr % 12;
        int gy = ty0 - 2 + iy, gx = tx0 - 2 + ix;
        float v = 0.f;
        if (gy >= 0 && gy < HH && gx >= 0 && gx < WW)
            v = dbase[(c * HH + gy) * WW + gx];
        sIn[i] = v;
    }
    __syncthreads();

    // build B: [j 0..79][n 0..127], stride 136 words, 16-bit halves
    {
        int n = tid >> 1, h2 = tid & 1;
        int y = n >> 3, x = n & 7;
        unsigned short* Bh = (unsigned short*)(smem + SM1_B);
        int c0 = h2 * 3;
        for (int c = c0; c < c0 + 3; c++) {
#pragma unroll
            for (int ky = 0; ky < 5; ky++)
#pragma unroll
                for (int kx = 0; kx < 5; kx++) {
                    int k = c * 25 + ky * 5 + kx;
                    __nv_bfloat16 b = __float2bfloat16(sIn[(c * 20 + y + ky) * 12 + x + kx]);
                    Bh[((k >> 1) * 136 + n) * 2 + (k & 1)] = *(unsigned short*)&b;
                }
        }
        if (h2) {
            uint32_t* Bw = (uint32_t*)(smem + SM1_B);
#pragma unroll
            for (int j = 75; j < 80; j++) Bw[j * 136 + n] = 0u;   // k=150..159 pad
        }
    }
    asm volatile("cp.async.wait_group 0;" ::: "memory");
    __syncthreads();

    // fragment addressing
    const uint32_t* Bp = (const uint32_t*)(smem + SM1_B);
    const int n0 = w * 16;
    const int boff = q * 136 + n0 + l4;
    const int row_l = lane & 15;
    const uint32_t a_off = (uint32_t)(row_l * 8 +
                          ((((lane >> 4) << 2) ^ (((row_l >> 2) & 1) << 2)))) * 4;
    const uint32_t aBase = sb + SM1_A + a_off;

    float acc[2][2][4];
#pragma unroll
    for (int mf = 0; mf < 2; mf++)
#pragma unroll
        for (int nf = 0; nf < 2; nf++)
#pragma unroll
            for (int r = 0; r < 4; r++) acc[mf][nf][r] = 0.f;

#pragma unroll
    for (int ks = 0; ks < 10; ks++) {
        uint32_t b0[2], b1[2];
#pragma unroll
        for (int nf = 0; nf < 2; nf++) {
            int o = boff + ks * 8 * 136 + nf * 8;
            b0[nf] = Bp[o];
            b1[nf] = Bp[o + 4 * 136];
        }
#pragma unroll
        for (int v = 0; v < 3; v++) {
            uint32_t a0[4], a1[4];
            uint32_t ab = aBase + (uint32_t)(ks * 3 + v) * 1024;
            ldmx4(a0, ab);
            ldmx4(a1, ab + 512);
#pragma unroll
            for (int nf = 0; nf < 2; nf++) {
                mma16816(acc[0][nf], a0[0], a0[1], a0[2], a0[3], b0[nf], b1[nf]);
                mma16816(acc[1][nf], a1[0], a1[1], a1[2], a1[3], b0[nf], b1[nf]);
            }
        }
    }

    // spike bits -> smem
    unsigned char* sSp = (unsigned char*)(smem + SM1_SP);
#pragma unroll
    for (int mf = 0; mf < 2; mf++)
#pragma unroll
        for (int nf = 0; nf < 2; nf++)
#pragma unroll
            for (int r = 0; r < 4; r++) {
                int f = 16 * mf + 8 * ((r >> 1) & 1) + l4;
                int px = n0 + 8 * nf + 2 * q + (r & 1);
                sSp[px * 32 + f] = (acc[mf][nf][r] > THR1) ? 1 : 0;
            }
    __syncthreads();

    // 2x2 max-pool (OR of spike bits) -> g_inp2
    for (int i = tid; i < 960; i += 256) {
        int f = i >> 5, pr = i & 31;          // f 0..29, pr 0..31
        int pyl = pr >> 2, pxl = pr & 3;      // pooled local 8x4
        int p00 = ((2 * pyl) * 8 + 2 * pxl) * 32 + f;
        unsigned char s = sSp[p00] | sSp[p00 + 32] | sSp[p00 + 256] | sSp[p00 + 288];
        g_inp2[((t * F1 + f) * IP + (ty0 / 2 + pyl + 1)) * IP + (tx0 / 2 + pxl + 1)] = (float)s;
    }
}

// ===================== conv2: mma.sync + cp.async pipeline + B reuse =====================
// grid (100 tiles, 2 f-halves, 15 t), block 256 (8 warps).
__global__ __launch_bounds__(256) void conv2_mma_k()
{
    extern __shared__ char smem[];
    const uint32_t sb = smem_u32(smem);
    const int t = blockIdx.z;
    const int half = blockIdx.y;
    const int tile = blockIdx.x;
    const int ty0 = (tile / 10) * 8;
    const int tx0 = (tile % 10) * 8;
    const int tid = threadIdx.x;
    const int w = tid >> 5;
    const int lane = tid & 31;
    const int q = lane & 3, l4 = lane >> 2;

    const char* gA = ((const char*)g_W2A) + (size_t)half * NKS * 3 * 4096;

    // prologue: prefetch stages 0,1
#pragma unroll
    for (int p = 0; p < 2; p++) {
        uint32_t dst = sb + SM2_A + p * 12288 + tid * 16;
        const char* src = gA + (size_t)p * 12288 + tid * 16;
#pragma unroll
        for (int i = 0; i < 3; i++)
            asm volatile("cp.async.cg.shared.global [%0], [%1], 16;"
                :: "r"(dst + i * 4096), "l"(src + (size_t)i * 4096));
        asm volatile("cp.async.commit_group;" ::: "memory");
    }

    // stage input window
    float* sIn = (float*)(smem + SM2_SIN);
    const float* ib = g_inp2 + (size_t)t * F1 * IP * IP;
    for (int i = tid; i < 3000; i += 256) {
        int c = i / 100, r = i % 100;
        sIn[i] = ib[((size_t)c * IP + (ty0 + r / 10)) * IP + (tx0 + r % 10)];
    }
    __syncthreads();

    // build B: packed bf16x2 [j=k/2 (136)][n=64] stride 72 words
    {
        int n = tid >> 2, qq = tid & 3;
        int py = n >> 3, px = n & 7;
        int c0 = (qq * 30) >> 2;
        int c1 = ((qq + 1) * 30) >> 2;
        unsigned short* Bh = (unsigned short*)(smem + SM2_B);
        for (int c = c0; c < c1; c++) {
#pragma unroll
            for (int ky = 0; ky < 3; ky++) {
#pragma unroll
                for (int kx = 0; kx < 3; kx++) {
                    int k = c * 9 + ky * 3 + kx;
                    __nv_bfloat16 b = __float2bfloat16(sIn[c * 100 + (py + ky) * 10 + px + kx]);
                    Bh[((k >> 1) * 72 + n) * 2 + (k & 1)] = *(unsigned short*)&b;
                }
            }
        }
        if (qq == 3) ((uint32_t*)(smem + SM2_B))[135 * 72 + n] = 0u;   // k=270,271 pad
    }

    // fragment addressing
    const int m0 = (w >> 1) * 32, n0 = (w & 1) * 32;
    const uint32_t* Bp = (const uint32_t*)(smem + SM2_B);
    const int boff = q * 72 + n0 + l4;
    const int row_l = m0 + (lane & 15);
    const uint32_t a_off = (uint32_t)(row_l * 8 +
                         ((((lane >> 4) << 2) ^ (((row_l >> 2) & 1) << 2)))) * 4;
    const uint32_t aBase = sb + SM2_A + a_off;

    float acc[2][4][4];
#pragma unroll
    for (int mf = 0; mf < 2; mf++)
#pragma unroll
        for (int nf = 0; nf < 4; nf++)
#pragma unroll
            for (int r = 0; r < 4; r++) acc[mf][nf][r] = 0.f;

    // main loop: ks outer (B reused), v inner
    for (int ks = 0; ks < NKS; ks++) {
        asm volatile("cp.async.wait_group 1;" ::: "memory");
        __syncthreads();

        uint32_t b0[4], b1[4];
#pragma unroll
        for (int nf = 0; nf < 4; nf++) {
            int o = boff + ks * 576 + nf * 8;
            b0[nf] = Bp[o];
            b1[nf] = Bp[o + 288];
        }
        uint32_t abase = aBase + (uint32_t)(ks % 3) * 12288;
#pragma unroll
        for (int v = 0; v < 3; v++) {
            uint32_t a0[4], a1[4];
            ldmx4(a0, abase + v * 4096);
            ldmx4(a1, abase + v * 4096 + 512);
#pragma unroll
            for (int nf = 0; nf < 4; nf++) {
                mma16816(acc[0][nf], a0[0], a0[1], a0[2], a0[3], b0[nf], b1[nf]);
                mma16816(acc[1][nf], a1[0], a1[1], a1[2], a1[3], b0[nf], b1[nf]);
            }
        }
        if (ks + 2 < NKS) {
            int nk = ks + 2;
            uint32_t dst = sb + SM2_A + (uint32_t)(nk % 3) * 12288 + tid * 16;
            const char* src = gA + (size_t)nk * 12288 + tid * 16;
#pragma unroll
            for (int i = 0; i < 3; i++)
                asm volatile("cp.async.cg.shared.global [%0], [%1], 16;"
                    :: "r"(dst + i * 4096), "l"(src + (size_t)i * 4096));
        }
        asm volatile("cp.async.commit_group;" ::: "memory");
    }

    // threshold in place
#pragma unroll
    for (int mf = 0; mf < 2; mf++)
#pragma unroll
        for (int nf = 0; nf < 4; nf++)
#pragma unroll
            for (int r = 0; r < 4; r++) {
                float v = acc[mf][nf][r];
                acc[mf][nf][r] = (v > THR2) ? v : 0.f;
            }

    // per-(t,hw) argmax keys: shfl pre-reduce over l4, atomicMax to global
#pragma unroll
    for (int nf = 0; nf < 4; nf++) {
#pragma unroll
        for (int lh = 0; lh < 2; lh++) {
            unsigned long long key = 0ull;
#pragma unroll
            for (int mf = 0; mf < 2; mf++)
#pragma unroll
                for (int hi = 0; hi < 2; hi++) {
                    float tv = acc[mf][nf][(hi << 1) | lh];
                    unsigned fg = (unsigned)(half * 128 + m0 + 16 * mf + 8 * hi + l4);
                    unsigned long long k =
                        ((unsigned long long)__float_as_uint(tv) << 32) | (255u - fg);
                    if (k > key) key = k;
                }
#pragma unroll
            for (int msk = 4; msk <= 16; msk <<= 1) {
                unsigned long long o = __shfl_xor_sync(0xffffffffu, key, msk);
                if (o > key) key = o;
            }
            if (l4 == 0) {
                int px = n0 + 8 * nf + 2 * q + lh;
                int hw = (ty0 + (px >> 3)) * PH + tx0 + (px & 7);
                atomicMax(&g_am[t * NHW + hw], key);
            }
        }
    }

    __syncthreads();   // all B reads done; reuse SM2_B as transpose buffer

    float* sD = (float*)(smem + SM2_B);           // [64 px][stride 132]
#pragma unroll
    for (int mf = 0; mf < 2; mf++)
#pragma unroll
        for (int nf = 0; nf < 4; nf++)
#pragma unroll
            for (int r = 0; r < 4; r++) {
                int fl = m0 + 16 * mf + 8 * ((r >> 1) & 1) + l4;
                int px = n0 + 8 * nf + 2 * q + (r & 1);
                sD[px * 132 + fl] = acc[mf][nf][r];
            }
    __syncthreads();
    {
        int pxl = tid >> 2;
        int fo = (tid & 3) * 32;
        int y = ty0 + (pxl >> 3), x = tx0 + (pxl & 7);
        float* o = g_pot2 + ((size_t)t * NHW + (size_t)(y * PH + x)) * FPAD + half * 128 + fo;
        const float* s = sD + pxl * 132 + fo;
#pragma unroll
        for (int j = 0; j < 8; j++)
            *(float4*)(o + j * 4) = *(const float4*)(s + j * 4);
    }
}

// ===================== pointwise inhibition (key-based) + sparse scatter =====================
__global__ __launch_bounds__(128) void inhib_k(float* __restrict__ out)
{
    int hw = blockIdx.x * 128 + threadIdx.x;
    if (hw >= NHW) return;

    int S = 0;
    unsigned long long klast = 0ull;
#pragma unroll
    for (int t = 0; t < T_; t++) {
        unsigned long long k = g_am[t * NHW + hw];
        if ((k >> 32) != 0ull) S++;
        if (t == T_ - 1) klast = k;
    }
    int clamp14 = ((klast >> 32) != 0ull) ? 1 : 0;
    int ft0 = T_ - S;
    if (ft0 < 0) ft0 = 0;
    if (ft0 > T_ - 1) ft0 = T_ - 1;
    unsigned long long kf = g_am[ft0 * NHW + hw];
    int wf = 255 - (int)(kf & 0xFFFFFFFFull);

    if (clamp14) {
        float pv[T_];
        int nsp = 0;
#pragma unroll
        for (int t = 0; t < T_; t++) {
            pv[t] = g_pot2[((size_t)t * NHW + hw) * FPAD + wf];
            if (pv[t] > 0.f) nsp++;
        }
        int ft = T_ - nsp;
        if (ft < 0) ft = 0;
        if (ft > T_ - 1) ft = T_ - 1;
        float fval = pv[ft];
#pragma unroll
        for (int t = 0; t < T_; t++) {
            if (pv[t] > 0.f) {
                size_t o = ((size_t)t * F2 + wf) * NHW + hw;
                out[o] = 1.f;
                out[(size_t)T_ * F2 * NHW + o] = pv[t];
            }
        }
        g_val[hw] = fval;
        g_nsp[hw] = nsp;
        g_wf[hw]  = wf;
        if (nsp > 0) atomicMax(&g_maxbits, __float_as_uint(fval));
    } else {
        g_val[hw] = 0.f;
        g_nsp[hw] = 0;
        g_wf[hw]  = 0;
    }
}

// ===================== k-WTA =====================
__global__ __launch_bounds__(1024) void winners_k(float* __restrict__ out)
{
    const int tid = threadIdx.x;
    __shared__ unsigned long long sred[32];

    float maxval = __uint_as_float(g_maxbits);
    float v15 = 15.f * maxval;

    float tot[7];
    int key[7], fh[7], hh[7], ww[7];
#pragma unroll
    for (int k = 0; k < 7; k++) {
        int idx = tid + k * 1024;
        if (idx < NHW) {
            int nsp = g_nsp[idx];
            float val = g_val[idx];
            int f = g_wf[idx];
            tot[k] = (nsp > 0) ? (float)nsp * (val + v15) : 0.f;
            fh[k] = f;
            hh[k] = idx / PH;
            ww[k] = idx % PH;
            key[k] = f * NHW + idx;
        } else {
            tot[k] = 0.f; key[k] = 0; fh[k] = -2; hh[k] = -100; ww[k] = -100;
        }
    }

    float* wout = out + (size_t)2 * T_ * F2 * NHW;

    for (int it = 0; it < KWTA; it++) {
        unsigned long long p = 0ull;
#pragma unroll
        for (int k = 0; k < 7; k++) {
            if (tot[k] > 0.f) {
                unsigned long long pk =
                    ((unsigned long long)__float_as_uint(tot[k]) << 32) |
                    (unsigned long long)(0x7FFFFFFFu - (unsigned)key[k]);
                if (pk > p) p = pk;
            }
        }
#pragma unroll
        for (int o = 16; o > 0; o >>= 1) {
            unsigned long long qq = __shfl_down_sync(0xffffffffu, p, o);
            if (qq > p) p = qq;
        }
        int warp = tid >> 5, lane = tid & 31;
        if (lane == 0) sred[warp] = p;
        __syncthreads();
        if (warp == 0) {
            p = (lane < 32) ? sred[lane] : 0ull;
#pragma unroll
            for (int o = 16; o > 0; o >>= 1) {
                unsigned long long qq = __shfl_down_sync(0xffffffffu, p, o);
                if (qq > p) p = qq;
            }
            if (lane == 0) sred[0] = p;
        }
        __syncthreads();
        unsigned long long best = sred[0];
        __syncthreads();

        if ((best >> 32) == 0ull) {
            if (tid == 0) {
                wout[it * 3 + 0] = -1.f;
                wout[it * 3 + 1] = -1.f;
                wout[it * 3 + 2] = -1.f;
            }
            continue;
        }
        int bkey = (int)(0x7FFFFFFFu - (unsigned)(best & 0xFFFFFFFFull));
        int bf = bkey / NHW;
        int bhw = bkey % NHW;
        int bh = bhw / PH, bw = bhw % PH;

        if (tid == 0) {
            wout[it * 3 + 0] = (float)bf;
            wout[it * 3 + 1] = (float)bh;
            wout[it * 3 + 2] = (float)bw;
        }

#pragma unroll
        for (int k = 0; k < 7; k++) {
            int dh = hh[k] - bh; if (dh < 0) dh = -dh;
            int dw = ww[k] - bw; if (dw < 0) dw = -dw;
            if (fh[k] == bf || (dh <= RADIUS && dw <= RADIUS)) tot[k] = 0.f;
        }
    }
}

// ===================== launch =====================
extern "C" void kernel_launch(void* const* d_in, const int* in_sizes, int n_in,
                              void* d_out, int out_size)
{
    const float* data = (const float*)d_in[0];
    const float* W1   = (const float*)d_in[1];
    const float* W2   = (const float*)d_in[2];
    float* out = (float*)d_out;

    cudaFuncSetAttribute(conv1_mma_k, cudaFuncAttributeMaxDynamicSharedMemorySize, SM1_TOTAL);
    cudaFuncSetAttribute(conv2_mma_k, cudaFuncAttributeMaxDynamicSharedMemorySize, SM2_TOTAL);

    prep_k<<<136, 256>>>(W1, W2);

    dim3 g1(200, T_);
    conv1_mma_k<<<g1, 256, SM1_TOTAL>>>(data, out, out_size / 4);

    dim3 g2(100, 2, T_);
    conv2_mma_k<<<g2, 256, SM2_TOTAL>>>();

    inhib_k<<<(NHW + 127) / 128, 128>>>(out);

    winners_k<<<1, 1024>>>(out);
}